// round 14
// baseline (speedup 1.0000x reference)
#include <cuda_runtime.h>
#include <cstdint>
#include <cstddef>

#define R_  8
#define K_  32
#define B_  1024
#define D_  256
#define L_  16
#define RK_ (R_ * K_)
#define BT_ 128
#define OSUM_SLOTS 32

// Scratch. g_loss is B-MAJOR: g_loss[b * RK + r*K + k]  (1 MB).
__device__ float g_loss[B_ * RK_];
__device__ float g_cnt[RK_];
__device__ float g_vsum[RK_];
__device__ float g_osum_p[R_ * OSUM_SLOTS];
__device__ unsigned int g_arrive;

// ---------------- packed f32x2 helpers (Blackwell FFMA2 path) ----------------

__device__ __forceinline__ void unpack2(unsigned long long p, float& lo, float& hi) {
    unsigned int a, b;
    asm("mov.b64 {%0, %1}, %2;" : "=r"(a), "=r"(b) : "l"(p));
    lo = __uint_as_float(a);
    hi = __uint_as_float(b);
}
__device__ __forceinline__ unsigned long long ffma2(unsigned long long a,
                                                    unsigned long long b,
                                                    unsigned long long c) {
    unsigned long long d;
    asm("fma.rn.f32x2 %0, %1, %2, %3;" : "=l"(d) : "l"(a), "l"(b), "l"(c));
    return d;
}

// ---------------------------------------------------------------------------
// Kernel 1: fused x_ = z @ Us^T and loss. grid = (B/BT, RK), 256 threads.
// Thread t: d-quad dq = t & 63, b-group bg = t >> 6 (32 b's each).
// REGISTER-DIET build targeting 3 CTAs/SM (24 warps, occ 37.5%):
//   - __launch_bounds__(256, 3)  (85-reg cap)
//   - 4 accumulator chains (not 8), q-register reuse, scalar loss math,
//     no manual unroll. Datapath math identical to the best (R8) variant.
// ---------------------------------------------------------------------------
__global__ __launch_bounds__(256, 3) void ksub_gemm_loss(
    const float* __restrict__ x,      // (B, D)
    const float* __restrict__ z,      // (R, K, B, L)
    const float* __restrict__ Us,     // (R, K, D, L)
    float* __restrict__ x_out)        // (R, K, B, D)
{
    const int tid = threadIdx.x;
    const int dq  = tid & 63;         // d-quad index, d = 4*dq
    const int bg  = tid >> 6;         // 0..3 b-group
    const int rk  = blockIdx.y;
    const int b0  = blockIdx.x * BT_;

    // Zero the stat partials once per launch (runs before ksub_assign).
    if (blockIdx.x == 0 && blockIdx.y == 0) {
        if (tid < RK_) { g_cnt[tid] = 0.f; g_vsum[tid] = 0.f; }
        if (tid < R_ * OSUM_SLOTS) g_osum_p[tid] = 0.f;
    }

    // z tile, natural layout: 128 * 16 floats = 8 KB.
    __shared__ __align__(16) float4 zs4[BT_ * 4];
    // per-(b, dq) loss partials; pad 68 -> row 272B (16B-aligned)
    __shared__ __align__(16) float arr[BT_][68];

    // ---- Us quad in natural packed pairs: u[d][j] = {u_{d,2j}, u_{d,2j+1}}
    unsigned long long u[4][8];
    {
        const ulonglong2* ug =
            reinterpret_cast<const ulonglong2*>(Us + ((size_t)rk * D_ + dq * 4) * L_);
        #pragma unroll
        for (int d = 0; d < 4; ++d) {
            #pragma unroll
            for (int q = 0; q < 4; ++q) {
                const ulonglong2 v = ug[d * 4 + q];
                u[d][q * 2 + 0] = v.x;
                u[d][q * 2 + 1] = v.y;
            }
        }
    }

    // ---- Stage z tile (contiguous copy)
    {
        const float4* zg =
            reinterpret_cast<const float4*>(z + ((size_t)rk * B_ + b0) * L_);
        zs4[tid]       = zg[tid];
        zs4[tid + 256] = zg[tid + 256];
    }
    __syncthreads();

    const float4* x4 =
        reinterpret_cast<const float4*>(x) + (size_t)b0 * (D_ / 4) + dq;
    float4* o4 =
        reinterpret_cast<float4*>(x_out) +
        ((size_t)rk * B_ + b0) * (D_ / 4) + dq;

    const ulonglong2* zr = reinterpret_cast<const ulonglong2*>(zs4);

    const int blo = bg * 32;
    #pragma unroll 1
    for (int b = blo; b < blo + 32; ++b) {
        // 4 chains (one per d); each chain touched every 4 instrs -> 8-cyc
        // dep distance >= lat 4. q registers reused between k-halves.
        unsigned long long acc0, acc1, acc2, acc3;

        ulonglong2 qa = zr[b * 4 + 0];
        ulonglong2 qb = zr[b * 4 + 1];

        acc0 = ffma2(qa.x, u[0][0], 0ull);
        acc1 = ffma2(qa.x, u[1][0], 0ull);
        acc2 = ffma2(qa.x, u[2][0], 0ull);
        acc3 = ffma2(qa.x, u[3][0], 0ull);
        acc0 = ffma2(qa.y, u[0][1], acc0);
        acc1 = ffma2(qa.y, u[1][1], acc1);
        acc2 = ffma2(qa.y, u[2][1], acc2);
        acc3 = ffma2(qa.y, u[3][1], acc3);
        acc0 = ffma2(qb.x, u[0][2], acc0);
        acc1 = ffma2(qb.x, u[1][2], acc1);
        acc2 = ffma2(qb.x, u[2][2], acc2);
        acc3 = ffma2(qb.x, u[3][2], acc3);
        acc0 = ffma2(qb.y, u[0][3], acc0);
        acc1 = ffma2(qb.y, u[1][3], acc1);
        acc2 = ffma2(qb.y, u[2][3], acc2);
        acc3 = ffma2(qb.y, u[3][3], acc3);

        qa = zr[b * 4 + 2];
        qb = zr[b * 4 + 3];

        acc0 = ffma2(qa.x, u[0][4], acc0);
        acc1 = ffma2(qa.x, u[1][4], acc1);
        acc2 = ffma2(qa.x, u[2][4], acc2);
        acc3 = ffma2(qa.x, u[3][4], acc3);
        acc0 = ffma2(qa.y, u[0][5], acc0);
        acc1 = ffma2(qa.y, u[1][5], acc1);
        acc2 = ffma2(qa.y, u[2][5], acc2);
        acc3 = ffma2(qa.y, u[3][5], acc3);
        acc0 = ffma2(qb.x, u[0][6], acc0);
        acc1 = ffma2(qb.x, u[1][6], acc1);
        acc2 = ffma2(qb.x, u[2][6], acc2);
        acc3 = ffma2(qb.x, u[3][6], acc3);
        acc0 = ffma2(qb.y, u[0][7], acc0);
        acc1 = ffma2(qb.y, u[1][7], acc1);
        acc2 = ffma2(qb.y, u[2][7], acc2);
        acc3 = ffma2(qb.y, u[3][7], acc3);

        // horizontal K-sums (unpack2 is register aliasing, no MOV cost)
        float l0, h0, l1, h1, l2, h2, l3, h3;
        unpack2(acc0, l0, h0);
        unpack2(acc1, l1, h1);
        unpack2(acc2, l2, h2);
        unpack2(acc3, l3, h3);
        const float v0 = l0 + h0, v1 = l1 + h1;
        const float v2 = l2 + h2, v3 = l3 + h3;

        // streaming store: x_ is write-once
        __stcs(o4 + (size_t)b * (D_ / 4), make_float4(v0, v1, v2, v3));

        const float4 xv = __ldg(x4 + (size_t)b * (D_ / 4));
        const float d0 = xv.x - v0, d1 = xv.y - v1;
        const float d2 = xv.z - v2, d3 = xv.w - v3;
        arr[b][dq] = fmaf(d3, d3, fmaf(d2, d2, fmaf(d1, d1, d0 * d0)));
    }
    __syncthreads();

    // ---- Deferred loss reduction: thread t < 128 sums arr[t][0..63].
    // B-MAJOR store: g_loss[b * RK + rk] (scattered 4B, L2-absorbed).
    if (tid < BT_) {
        const float4* row = reinterpret_cast<const float4*>(arr[tid]);
        float4 s0 = row[0];
        #pragma unroll
        for (int j = 1; j < 16; ++j) {
            const float4 v = row[j];
            s0.x += v.x; s0.y += v.y; s0.z += v.z; s0.w += v.w;
        }
        g_loss[(size_t)(b0 + tid) * RK_ + rk] =
            0.5f * ((s0.x + s0.y) + (s0.z + s0.w));
    }
}

// ---------------------------------------------------------------------------
// Kernel 2: warp per (b, r): lane = k. Coalesced 128B loss read (b-major),
// shuffle top-2 (min), coalesced one-hot row, de-contended atomics.
// grid = 2048 blocks x 128 threads. Last block runs the finalize.
// ---------------------------------------------------------------------------
__global__ __launch_bounds__(128) void ksub_assign(
    const float* __restrict__ c_mean_in,   // (R, K)
    const float* __restrict__ value_in,    // (R, K)
    float* __restrict__ c_out,             // (B, R, K)
    float* __restrict__ obj_out,           // (R,)
    float* __restrict__ obj_mean,          // (1,)
    float* __restrict__ new_c_mean,        // (R, K)
    float* __restrict__ new_value)         // (R, K)
{
    const int t    = threadIdx.x;
    const int lane = t & 31;
    const int widx = blockIdx.x * 4 + (t >> 5);   // 0..8191
    const int r    = widx & 7;
    const int b    = widx >> 3;

    const float l = g_loss[(size_t)b * RK_ + r * K_ + lane];

    // argmin with lowest-index tie-break (matches jax top_k ordering)
    float mv = l; int mi = lane;
    #pragma unroll
    for (int off = 16; off >= 1; off >>= 1) {
        const float ov = __shfl_xor_sync(0xffffffffu, mv, off);
        const int   oi = __shfl_xor_sync(0xffffffffu, mi, off);
        if (ov < mv || (ov == mv && oi < mi)) { mv = ov; mi = oi; }
    }
    float m2 = (lane == mi) ? 3.402823466e38f : l;
    #pragma unroll
    for (int off = 16; off >= 1; off >>= 1)
        m2 = fminf(m2, __shfl_xor_sync(0xffffffffu, m2, off));

    c_out[((size_t)b * R_ + r) * K_ + lane] = (lane == mi) ? 1.0f : 0.0f;

    if (lane == 0) {
        atomicAdd(&g_cnt[r * K_ + mi], 1.0f);
        atomicAdd(&g_vsum[r * K_ + mi], m2 - mv);
        atomicAdd(&g_osum_p[r * OSUM_SLOTS + (blockIdx.x & (OSUM_SLOTS - 1))], mv);
    }

    // ---- last-block finalize
    __shared__ int is_last;
    __syncthreads();
    if (t == 0) {
        __threadfence();
        is_last = (atomicAdd(&g_arrive, 1u) == (unsigned)(gridDim.x - 1));
    }
    __syncthreads();
    if (!is_last) return;
    __threadfence();

    const float invB = 1.0f / (float)B_;
    for (int i = t; i < RK_; i += 128) {
        new_c_mean[i] = 0.9f * c_mean_in[i] + 0.1f * (__ldcg(&g_cnt[i])  * invB);
        new_value [i] = 0.9f * value_in [i] + 0.1f * (__ldcg(&g_vsum[i]) * invB);
    }
    __shared__ float obj_sh[R_];
    if (t < R_) {
        float s = 0.f;
        #pragma unroll
        for (int j = 0; j < OSUM_SLOTS; ++j)
            s += __ldcg(&g_osum_p[t * OSUM_SLOTS + j]);
        const float o = s * invB;
        obj_out[t] = o;
        obj_sh[t] = o;
    }
    __syncthreads();
    if (t == 0) {
        float s = 0.f;
        #pragma unroll
        for (int rr = 0; rr < R_; rr++) s += obj_sh[rr];
        *obj_mean = s * (1.0f / (float)R_);
        g_arrive = 0;   // reset for next replay
    }
}

// ---------------------------------------------------------------------------
extern "C" void kernel_launch(void* const* d_in, const int* in_sizes, int n_in,
                              void* d_out, int out_size)
{
    (void)in_sizes; (void)n_in; (void)out_size;
    const float* x   = (const float*)d_in[0];   // (B, D)
    const float* z   = (const float*)d_in[1];   // (R, K, B, L)
    const float* Us  = (const float*)d_in[2];   // (R, K, D, L)
    const float* cm  = (const float*)d_in[3];   // (R, K)
    const float* val = (const float*)d_in[4];   // (R, K)

    float* out      = (float*)d_out;
    float* x_out    = out;                                   // 67108864
    float* c_out    = x_out + (size_t)RK_ * B_ * D_;         //   262144
    float* obj_out  = c_out + (size_t)B_ * R_ * K_;          //        8
    float* obj_mean = obj_out + R_;                          //        1
    float* ncm      = obj_mean + 1;                          //      256
    float* nval     = ncm + RK_;                             //      256

    dim3 g1(B_ / BT_, RK_);
    ksub_gemm_loss<<<g1, 256>>>(x, z, Us, x_out);
    ksub_assign<<<2048, 128>>>(cm, val, c_out, obj_out, obj_mean, ncm, nval);
}

// round 15
// speedup vs baseline: 1.1575x; 1.1575x over previous
#include <cuda_runtime.h>
#include <cstdint>
#include <cstddef>

#define R_  8
#define K_  32
#define B_  1024
#define D_  256
#define L_  16
#define RK_ (R_ * K_)
#define BT_ 128
#define OSUM_SLOTS 32

// Scratch. g_loss is B-MAJOR: g_loss[b * RK + r*K + k]  (1 MB).
__device__ float g_loss[B_ * RK_];
__device__ float g_cnt[RK_];
__device__ float g_vsum[RK_];
__device__ float g_osum_p[R_ * OSUM_SLOTS];
__device__ unsigned int g_arrive;

// ---------------- packed f32x2 helpers (Blackwell FFMA2 path) ----------------

__device__ __forceinline__ void unpack2(unsigned long long p, float& lo, float& hi) {
    unsigned int a, b;
    asm("mov.b64 {%0, %1}, %2;" : "=r"(a), "=r"(b) : "l"(p));
    lo = __uint_as_float(a);
    hi = __uint_as_float(b);
}
__device__ __forceinline__ unsigned long long ffma2(unsigned long long a,
                                                    unsigned long long b,
                                                    unsigned long long c) {
    unsigned long long d;
    asm("fma.rn.f32x2 %0, %1, %2, %3;" : "=l"(d) : "l"(a), "l"(b), "l"(c));
    return d;
}
__device__ __forceinline__ unsigned long long fadd2(unsigned long long a,
                                                    unsigned long long b) {
    unsigned long long d;
    asm("add.rn.f32x2 %0, %1, %2;" : "=l"(d) : "l"(a), "l"(b));
    return d;
}

// ---------------------------------------------------------------------------
// Kernel 1: fused x_ = z @ Us^T and loss. grid = (B/BT, RK), 256 threads.
// EXACT R8 configuration (best measured: K1 ~89.5us): 8 FFMA2 chains,
// launch_bounds(256,2) (116 regs, no spills), scalar loss math.
// ---------------------------------------------------------------------------
__global__ __launch_bounds__(256, 2) void ksub_gemm_loss(
    const float* __restrict__ x,      // (B, D)
    const float* __restrict__ z,      // (R, K, B, L)
    const float* __restrict__ Us,     // (R, K, D, L)
    float* __restrict__ x_out)        // (R, K, B, D)
{
    const int tid = threadIdx.x;
    const int dq  = tid & 63;         // d-quad index, d = 4*dq
    const int bg  = tid >> 6;         // 0..3 b-group
    const int rk  = blockIdx.y;
    const int b0  = blockIdx.x * BT_;

    // Zero the stat partials once per launch (runs before ksub_assign).
    if (blockIdx.x == 0 && blockIdx.y == 0) {
        if (tid < RK_) { g_cnt[tid] = 0.f; g_vsum[tid] = 0.f; }
        if (tid < R_ * OSUM_SLOTS) g_osum_p[tid] = 0.f;
    }

    // z tile, natural layout: 128 * 16 floats = 8 KB.
    __shared__ __align__(16) float4 zs4[BT_ * 4];
    // per-(b, dq) loss partials; pad 68 -> row 272B (16B-aligned)
    __shared__ __align__(16) float arr[BT_][68];

    // ---- Us quad in natural packed pairs: u[d][j] = {u_{d,2j}, u_{d,2j+1}}
    unsigned long long u[4][8];
    {
        const ulonglong2* ug =
            reinterpret_cast<const ulonglong2*>(Us + ((size_t)rk * D_ + dq * 4) * L_);
        #pragma unroll
        for (int d = 0; d < 4; ++d) {
            #pragma unroll
            for (int q = 0; q < 4; ++q) {
                const ulonglong2 v = ug[d * 4 + q];
                u[d][q * 2 + 0] = v.x;
                u[d][q * 2 + 1] = v.y;
            }
        }
    }

    // ---- Stage z tile (contiguous copy)
    {
        const float4* zg =
            reinterpret_cast<const float4*>(z + ((size_t)rk * B_ + b0) * L_);
        zs4[tid]       = zg[tid];
        zs4[tid + 256] = zg[tid + 256];
    }
    __syncthreads();

    const float4* x4 =
        reinterpret_cast<const float4*>(x) + (size_t)b0 * (D_ / 4) + dq;
    float4* o4 =
        reinterpret_cast<float4*>(x_out) +
        ((size_t)rk * B_ + b0) * (D_ / 4) + dq;

    const ulonglong2* zr = reinterpret_cast<const ulonglong2*>(zs4);

    const int blo = bg * 32;
    #pragma unroll 2
    for (int b = blo; b < blo + 32; ++b) {
        // 8 natural z pairs via 4 uniform broadcast LDS.128
        const ulonglong2 q0 = zr[b * 4 + 0];
        const ulonglong2 q1 = zr[b * 4 + 1];
        const ulonglong2 q2 = zr[b * 4 + 2];
        const ulonglong2 q3 = zr[b * 4 + 3];

        // 8 independent chains (accA/accB per d), dep distance 8 >= lat 4
        unsigned long long accA0 = 0ull, accB0 = 0ull;
        unsigned long long accA1 = 0ull, accB1 = 0ull;
        unsigned long long accA2 = 0ull, accB2 = 0ull;
        unsigned long long accA3 = 0ull, accB3 = 0ull;

        accA0 = ffma2(q0.x, u[0][0], accA0);
        accA1 = ffma2(q0.x, u[1][0], accA1);
        accA2 = ffma2(q0.x, u[2][0], accA2);
        accA3 = ffma2(q0.x, u[3][0], accA3);
        accB0 = ffma2(q0.y, u[0][1], accB0);
        accB1 = ffma2(q0.y, u[1][1], accB1);
        accB2 = ffma2(q0.y, u[2][1], accB2);
        accB3 = ffma2(q0.y, u[3][1], accB3);

        accA0 = ffma2(q1.x, u[0][2], accA0);
        accA1 = ffma2(q1.x, u[1][2], accA1);
        accA2 = ffma2(q1.x, u[2][2], accA2);
        accA3 = ffma2(q1.x, u[3][2], accA3);
        accB0 = ffma2(q1.y, u[0][3], accB0);
        accB1 = ffma2(q1.y, u[1][3], accB1);
        accB2 = ffma2(q1.y, u[2][3], accB2);
        accB3 = ffma2(q1.y, u[3][3], accB3);

        accA0 = ffma2(q2.x, u[0][4], accA0);
        accA1 = ffma2(q2.x, u[1][4], accA1);
        accA2 = ffma2(q2.x, u[2][4], accA2);
        accA3 = ffma2(q2.x, u[3][4], accA3);
        accB0 = ffma2(q2.y, u[0][5], accB0);
        accB1 = ffma2(q2.y, u[1][5], accB1);
        accB2 = ffma2(q2.y, u[2][5], accB2);
        accB3 = ffma2(q2.y, u[3][5], accB3);

        accA0 = ffma2(q3.x, u[0][6], accA0);
        accA1 = ffma2(q3.x, u[1][6], accA1);
        accA2 = ffma2(q3.x, u[2][6], accA2);
        accA3 = ffma2(q3.x, u[3][6], accA3);
        accB0 = ffma2(q3.y, u[0][7], accB0);
        accB1 = ffma2(q3.y, u[1][7], accB1);
        accB2 = ffma2(q3.y, u[2][7], accB2);
        accB3 = ffma2(q3.y, u[3][7], accB3);

        const unsigned long long s0 = fadd2(accA0, accB0);
        const unsigned long long s1 = fadd2(accA1, accB1);
        const unsigned long long s2 = fadd2(accA2, accB2);
        const unsigned long long s3 = fadd2(accA3, accB3);

        float l0, h0, l1, h1, l2, h2, l3, h3;
        unpack2(s0, l0, h0);
        unpack2(s1, l1, h1);
        unpack2(s2, l2, h2);
        unpack2(s3, l3, h3);
        const float v0 = l0 + h0, v1 = l1 + h1;
        const float v2 = l2 + h2, v3 = l3 + h3;

        // streaming store: x_ is write-once
        __stcs(o4 + (size_t)b * (D_ / 4), make_float4(v0, v1, v2, v3));

        const float4 xv = __ldg(x4 + (size_t)b * (D_ / 4));
        const float d0 = xv.x - v0, d1 = xv.y - v1;
        const float d2 = xv.z - v2, d3 = xv.w - v3;
        arr[b][dq] = fmaf(d3, d3, fmaf(d2, d2, fmaf(d1, d1, d0 * d0)));
    }
    __syncthreads();

    // ---- Deferred loss reduction: thread t < 128 sums arr[t][0..63].
    // B-MAJOR store: g_loss[b * RK + rk] (scattered 4B, L2-absorbed).
    if (tid < BT_) {
        const float4* row = reinterpret_cast<const float4*>(arr[tid]);
        float4 s0 = row[0];
        #pragma unroll
        for (int j = 1; j < 16; ++j) {
            const float4 v = row[j];
            s0.x += v.x; s0.y += v.y; s0.z += v.z; s0.w += v.w;
        }
        g_loss[(size_t)(b0 + tid) * RK_ + rk] =
            0.5f * ((s0.x + s0.y) + (s0.z + s0.w));
    }
}

// ---------------------------------------------------------------------------
// Kernel 2: THREAD per (b, r) item — zero shuffles. 32 blocks x 256 threads.
// Each thread: 8 front-batched LDG.128 of its 32-float loss row, in-register
// strict-< top-2 scan (lowest-index ties = jax top_k), 8 STG.128 one-hot row,
// 3 de-contended atomics. Last block runs the finalize.
// ---------------------------------------------------------------------------
__global__ __launch_bounds__(256) void ksub_assign(
    const float* __restrict__ c_mean_in,   // (R, K)
    const float* __restrict__ value_in,    // (R, K)
    float* __restrict__ c_out,             // (B, R, K)
    float* __restrict__ obj_out,           // (R,)
    float* __restrict__ obj_mean,          // (1,)
    float* __restrict__ new_c_mean,        // (R, K)
    float* __restrict__ new_value)         // (R, K)
{
    const int t   = threadIdx.x;
    const int idx = blockIdx.x * 256 + t;   // 0..8191
    const int r   = idx & 7;
    const int b   = idx >> 3;

    // ---- load the 32-float loss row, front-batched (MLP = 8)
    const float4* lrow =
        reinterpret_cast<const float4*>(g_loss + (size_t)b * RK_ + r * K_);
    float4 v[8];
    #pragma unroll
    for (int q = 0; q < 8; ++q) v[q] = __ldg(lrow + q);

    // ---- in-register top-2 (min) with lowest-index tie-break
    float m1 = 3.402823466e38f, m2 = 3.402823466e38f;
    int g = 0;
    #pragma unroll
    for (int q = 0; q < 8; ++q) {
        const float e0 = v[q].x, e1 = v[q].y, e2 = v[q].z, e3 = v[q].w;
        if (e0 < m1) { m2 = m1; m1 = e0; g = q * 4 + 0; } else if (e0 < m2) m2 = e0;
        if (e1 < m1) { m2 = m1; m1 = e1; g = q * 4 + 1; } else if (e1 < m2) m2 = e1;
        if (e2 < m1) { m2 = m1; m1 = e2; g = q * 4 + 2; } else if (e2 < m2) m2 = e2;
        if (e3 < m1) { m2 = m1; m1 = e3; g = q * 4 + 3; } else if (e3 < m2) m2 = e3;
    }

    // ---- one-hot row c[b, r, :]
    float* crow = c_out + ((size_t)b * R_ + r) * K_;
    const float4 z4 = make_float4(0.f, 0.f, 0.f, 0.f);
    #pragma unroll
    for (int q = 0; q < 8; ++q)
        reinterpret_cast<float4*>(crow)[q] = z4;
    crow[g] = 1.0f;

    // ---- stats (3 atomics per item; ~32 adds per address)
    atomicAdd(&g_cnt[r * K_ + g], 1.0f);
    atomicAdd(&g_vsum[r * K_ + g], m2 - m1);
    atomicAdd(&g_osum_p[r * OSUM_SLOTS + (t & (OSUM_SLOTS - 1))], m1);

    // ---- last-block finalize
    __shared__ int is_last;
    __syncthreads();
    if (t == 0) {
        __threadfence();
        is_last = (atomicAdd(&g_arrive, 1u) == (unsigned)(gridDim.x - 1));
    }
    __syncthreads();
    if (!is_last) return;
    __threadfence();

    const float invB = 1.0f / (float)B_;
    for (int i = t; i < RK_; i += 256) {
        new_c_mean[i] = 0.9f * c_mean_in[i] + 0.1f * (__ldcg(&g_cnt[i])  * invB);
        new_value [i] = 0.9f * value_in [i] + 0.1f * (__ldcg(&g_vsum[i]) * invB);
    }
    __shared__ float obj_sh[R_];
    if (t < R_) {
        float s = 0.f;
        #pragma unroll
        for (int j = 0; j < OSUM_SLOTS; ++j)
            s += __ldcg(&g_osum_p[t * OSUM_SLOTS + j]);
        const float o = s * invB;
        obj_out[t] = o;
        obj_sh[t] = o;
    }
    __syncthreads();
    if (t == 0) {
        float s = 0.f;
        #pragma unroll
        for (int rr = 0; rr < R_; rr++) s += obj_sh[rr];
        *obj_mean = s * (1.0f / (float)R_);
        g_arrive = 0;   // reset for next replay
    }
}

// ---------------------------------------------------------------------------
extern "C" void kernel_launch(void* const* d_in, const int* in_sizes, int n_in,
                              void* d_out, int out_size)
{
    (void)in_sizes; (void)n_in; (void)out_size;
    const float* x   = (const float*)d_in[0];   // (B, D)
    const float* z   = (const float*)d_in[1];   // (R, K, B, L)
    const float* Us  = (const float*)d_in[2];   // (R, K, D, L)
    const float* cm  = (const float*)d_in[3];   // (R, K)
    const float* val = (const float*)d_in[4];   // (R, K)

    float* out      = (float*)d_out;
    float* x_out    = out;                                   // 67108864
    float* c_out    = x_out + (size_t)RK_ * B_ * D_;         //   262144
    float* obj_out  = c_out + (size_t)B_ * R_ * K_;          //        8
    float* obj_mean = obj_out + R_;                          //        1
    float* ncm      = obj_mean + 1;                          //      256
    float* nval     = ncm + RK_;                             //      256

    dim3 g1(B_ / BT_, RK_);
    ksub_gemm_loss<<<g1, 256>>>(x, z, Us, x_out);
    ksub_assign<<<32, 256>>>(cm, val, c_out, obj_out, obj_mean, ncm, nval);
}